// round 5
// baseline (speedup 1.0000x reference)
#include <cuda_runtime.h>
#include <cuda_fp16.h>
#include <math.h>

// Problem constants: N=8, C=3, R=8, P=512*512, n_iter=3
#define P_    262144
#define P4_   65536        // float4 count per plane
#define PH2_  131072       // float2 / half2-pair count per plane
#define EPS_  1e-10f
#define NB    440          // total blocks (8 n-groups x 55)
#define BPN   55
#define NTHR  128

typedef unsigned long long u64;

// ---- device globals (no allocations allowed) ----
__device__ float    g_stats[3 * 544];     // per iter, per n: [0,8) sum, [8,32) XD, [32,68) gram-tri
__device__ float    g_meanx[NB * 3];
__device__ unsigned g_count = 0;
__device__ unsigned g_sense = 0;
// fp16 Dt scratch, layout [n][rp][p]: plane rp holds half2 {Dt[2rp], Dt[2rp+1]} per point
__device__ __half2  g_dt[(size_t)32 * PH2_ * 2];

// ---- packed f32x2 helpers ----
struct F2 { float lo, hi; };
__device__ __forceinline__ u64 pk2(float lo, float hi) {
    u64 r;
    asm("mov.b64 %0, {%1, %2};" : "=l"(r) : "r"(__float_as_uint(lo)), "r"(__float_as_uint(hi)));
    return r;
}
__device__ __forceinline__ F2 un2(u64 v) {
    unsigned a, b;
    asm("mov.b64 {%0, %1}, %2;" : "=r"(a), "=r"(b) : "l"(v));
    F2 f; f.lo = __uint_as_float(a); f.hi = __uint_as_float(b); return f;
}
__device__ __forceinline__ u64 fma2_(u64 a, u64 b, u64 c) {
    u64 d; asm("fma.rn.f32x2 %0, %1, %2, %3;" : "=l"(d) : "l"(a), "l"(b), "l"(c)); return d;
}
__device__ __forceinline__ u64 mul2_(u64 a, u64 b) {
    u64 d; asm("mul.rn.f32x2 %0, %1, %2;" : "=l"(d) : "l"(a), "l"(b)); return d;
}
__device__ __forceinline__ u64 add2_(u64 a, u64 b) {
    u64 d; asm("add.rn.f32x2 %0, %1, %2;" : "=l"(d) : "l"(a), "l"(b)); return d;
}
__device__ __forceinline__ u64 h2f2(unsigned h) {
    __half2 hh = *reinterpret_cast<__half2*>(&h);
    float2 f = __half22float2(hh);
    return pk2(f.x, f.y);
}
__device__ __forceinline__ unsigned f22h(u64 v) {
    F2 f = un2(v);
    __half2 h = __floats2half2_rn(f.lo, f.hi);
    return *reinterpret_cast<unsigned*>(&h);
}
__device__ __forceinline__ u64 relu2(u64 v) {
    F2 f = un2(v);
    return pk2(fmaxf(f.lo, 0.f), fmaxf(f.hi, 0.f));
}
__device__ __forceinline__ int triIdx(int r, int r2) {   // r <= r2
    return r * 8 - (r * (r - 1)) / 2 + (r2 - r);
}
__device__ __forceinline__ unsigned ld_acq(unsigned* p) {
    unsigned v;
    asm volatile("ld.acquire.gpu.u32 %0, [%1];" : "=r"(v) : "l"(p) : "memory");
    return v;
}
// grid-wide sense-reversal barrier; all NB blocks co-resident by construction
__device__ __forceinline__ void gridsync() {
    __threadfence();
    __syncthreads();
    if (threadIdx.x == 0) {
        unsigned s0 = ld_acq(&g_sense);
        unsigned old = atomicAdd(&g_count, 1u);
        if (old == NB - 1) {
            atomicExch(&g_count, 0u);
            __threadfence();
            atomicAdd(&g_sense, 1u);
        } else {
            while (ld_acq(&g_sense) == s0) __nanosleep(64);
        }
    }
    __syncthreads();
}

// iterA: StS, tauD, x0(own n), cnst(own n). Redundant per block.
__device__ __forceinline__ void do_iterA(int tid, int n,
        const float* sS, const float* sMX, const float* f_own, const float* acc_own,
        float* cn_own, float* sStS, float* x0c, float* sh_tauD, float lam, float gam) {
    if (tid < 64) {
        int r = tid >> 3, r2 = tid & 7;
        float a = 0.f;
        #pragma unroll
        for (int c = 0; c < 3; c++) a += sS[c * 8 + r] * sS[c * 8 + r2];
        sStS[tid] = a;
    }
    __syncthreads();
    if (tid == 0) {
        float s = 0.f;
        #pragma unroll
        for (int r = 0; r < 8; r++) s += sStS[r * 8 + r];
        *sh_tauD = 1.f / s;
    }
    __syncthreads();
    float tauD = *sh_tauD;
    if (tid < 3) {
        float acc = sMX[n * 3 + tid];
        #pragma unroll
        for (int r = 0; r < 8; r++) acc += sS[tid * 8 + r] * f_own[r] * acc_own[r];
        x0c[tid] = acc * (1.f / (float)P_);
    }
    __syncthreads();
    if (tid < 8) {
        int r = tid;
        float bb = 0.f;
        #pragma unroll
        for (int c = 0; c < 3; c++) bb += sS[c * 8 + r] * x0c[c];
        cn_own[r] = tauD * bb - lam * gam * tauD * sqrtf(sStS[r * 8 + r]);
    }
    __syncthreads();
}

// ---------------------------------------------------------------------------
// run_pass: fused D-update + prox + stats, r-pair packed with f32x2.
//   MODE 0: first iter (no Dt read, store). MODE 1: read + store. MODE 2: read only.
// ---------------------------------------------------------------------------
template<int MODE>
__device__ __forceinline__ void run_pass(
    const float2* __restrict__ Xp2, uint2* __restrict__ Dq,
    int s2, int e2, int tid, int lane, int wid,
    const float* sS, const float* f_own, const float* cn_own, float tauD,
    float* sred, float* dst)
{
    u64 Sp[12], frp[4], cnp[4];
    #pragma unroll
    for (int c = 0; c < 3; c++)
        #pragma unroll
        for (int rp = 0; rp < 4; rp++)
            Sp[c * 4 + rp] = pk2(sS[c * 8 + 2 * rp], sS[c * 8 + 2 * rp + 1]);
    #pragma unroll
    for (int rp = 0; rp < 4; rp++) {
        frp[rp] = pk2(f_own[2 * rp], f_own[2 * rp + 1]);
        cnp[rp] = pk2(cn_own[2 * rp], cn_own[2 * rp + 1]);
    }
    const float ntauD = -tauD;

    u64 a_sp[4], a_xp[12], a_gp[20];
    #pragma unroll
    for (int k = 0; k < 4; k++)  a_sp[k] = 0ull;
    #pragma unroll
    for (int k = 0; k < 12; k++) a_xp[k] = 0ull;
    #pragma unroll
    for (int k = 0; k < 20; k++) a_gp[k] = 0ull;

    for (int i = s2 + tid; i < e2; i += NTHR) {
        float2 xv0 = Xp2[i], xv1 = Xp2[i + PH2_], xv2 = Xp2[i + 2 * PH2_];
        uint2 dq[4], st[4];
        if (MODE != 0) {
            #pragma unroll
            for (int rp = 0; rp < 4; rp++) dq[rp] = Dq[i + rp * PH2_];
        }
        #pragma unroll
        for (int j = 0; j < 2; j++) {
            float x0 = j ? xv0.y : xv0.x;
            float x1 = j ? xv1.y : xv1.x;
            float x2 = j ? xv2.y : xv2.x;
            u64 v[4];
            if (MODE != 0) {
                u64 dp[4];
                #pragma unroll
                for (int rp = 0; rp < 4; rp++)
                    dp[rp] = mul2_(frp[rp], h2f2(j ? dq[rp].y : dq[rp].x));   // de r-pairs
                u64 t0p = mul2_(Sp[0], dp[0]);
                t0p = fma2_(Sp[1], dp[1], t0p); t0p = fma2_(Sp[2], dp[2], t0p); t0p = fma2_(Sp[3], dp[3], t0p);
                u64 t1p = mul2_(Sp[4], dp[0]);
                t1p = fma2_(Sp[5], dp[1], t1p); t1p = fma2_(Sp[6], dp[2], t1p); t1p = fma2_(Sp[7], dp[3], t1p);
                u64 t2p = mul2_(Sp[8], dp[0]);
                t2p = fma2_(Sp[9], dp[1], t2p); t2p = fma2_(Sp[10], dp[2], t2p); t2p = fma2_(Sp[11], dp[3], t2p);
                F2 h0 = un2(t0p), h1 = un2(t1p), h2 = un2(t2p);
                float tc0 = ntauD * (x0 + h0.lo + h0.hi);
                float tc1 = ntauD * (x1 + h1.lo + h1.hi);
                float tc2 = ntauD * (x2 + h2.lo + h2.hi);
                u64 tb0 = pk2(tc0, tc0), tb1 = pk2(tc1, tc1), tb2 = pk2(tc2, tc2);
                #pragma unroll
                for (int rp = 0; rp < 4; rp++) {
                    u64 va = fma2_(tb0, Sp[rp], cnp[rp]);
                    va = fma2_(tb1, Sp[4 + rp], va);
                    va = fma2_(tb2, Sp[8 + rp], va);
                    va = add2_(va, dp[rp]);
                    v[rp] = relu2(va);
                }
            } else {
                float tc0 = ntauD * x0, tc1 = ntauD * x1, tc2 = ntauD * x2;
                u64 tb0 = pk2(tc0, tc0), tb1 = pk2(tc1, tc1), tb2 = pk2(tc2, tc2);
                #pragma unroll
                for (int rp = 0; rp < 4; rp++) {
                    u64 va = fma2_(tb0, Sp[rp], cnp[rp]);
                    va = fma2_(tb1, Sp[4 + rp], va);
                    va = fma2_(tb2, Sp[8 + rp], va);
                    v[rp] = relu2(va);
                }
            }
            // ---- stats (packed over r-pairs) ----
            #pragma unroll
            for (int rp = 0; rp < 4; rp++) a_sp[rp] = add2_(a_sp[rp], v[rp]);
            u64 xb0 = pk2(x0, x0), xb1 = pk2(x1, x1), xb2 = pk2(x2, x2);
            #pragma unroll
            for (int rp = 0; rp < 4; rp++) {
                a_xp[rp]     = fma2_(xb0, v[rp], a_xp[rp]);
                a_xp[4 + rp] = fma2_(xb1, v[rp], a_xp[4 + rp]);
                a_xp[8 + rp] = fma2_(xb2, v[rp], a_xp[8 + rp]);
            }
            {
                F2 vf[4];
                #pragma unroll
                for (int rp = 0; rp < 4; rp++) vf[rp] = un2(v[rp]);
                int gi = 0;
                #pragma unroll
                for (int r = 0; r < 8; r++) {
                    float vr = (r & 1) ? vf[r >> 1].hi : vf[r >> 1].lo;
                    u64 vb = pk2(vr, vr);
                    #pragma unroll
                    for (int rp = r >> 1; rp < 4; rp++) { a_gp[gi] = fma2_(vb, v[rp], a_gp[gi]); gi++; }
                }
            }
            if (MODE != 2) {
                #pragma unroll
                for (int rp = 0; rp < 4; rp++) {
                    unsigned h = f22h(v[rp]);
                    if (j) st[rp].y = h; else st[rp].x = h;
                }
            }
        }
        if (MODE != 2) {
            #pragma unroll
            for (int rp = 0; rp < 4; rp++) Dq[i + rp * PH2_] = st[rp];
        }
    }

    // ---- decode packed accumulators -> 68 scalars in g_stats order ----
    float a68[68];
    #pragma unroll
    for (int rp = 0; rp < 4; rp++) {
        F2 s = un2(a_sp[rp]); a68[2 * rp] = s.lo; a68[2 * rp + 1] = s.hi;
    }
    #pragma unroll
    for (int c = 0; c < 3; c++)
        #pragma unroll
        for (int rp = 0; rp < 4; rp++) {
            F2 s = un2(a_xp[c * 4 + rp]);
            a68[8 + c * 8 + 2 * rp] = s.lo; a68[8 + c * 8 + 2 * rp + 1] = s.hi;
        }
    {
        int gi = 0;
        #pragma unroll
        for (int r = 0; r < 8; r++)
            #pragma unroll
            for (int rp = r >> 1; rp < 4; rp++) {
                F2 s = un2(a_gp[gi]); gi++;
                if (2 * rp >= r) a68[32 + triIdx(r, 2 * rp)] = s.lo;
                a68[32 + triIdx(r, 2 * rp + 1)] = s.hi;
            }
    }
    // ---- flush: warp shuffle -> smem -> one atomic per value ----
    __syncthreads();
    #pragma unroll
    for (int k = 0; k < 68; k++) {
        float vv = a68[k];
        #pragma unroll
        for (int o = 16; o; o >>= 1) vv += __shfl_xor_sync(~0u, vv, o);
        if (lane == 0) sred[wid * 68 + k] = vv;
    }
    __syncthreads();
    if (tid < 68) {
        float s = sred[tid] + sred[68 + tid] + sred[136 + tid] + sred[204 + tid];
        atomicAdd(&dst[tid], s);
    }
}

__global__ void __launch_bounds__(NTHR, 3)
k_all(const float* __restrict__ X, const float* __restrict__ Sin,
      const float* __restrict__ gamma_, const float* __restrict__ lam_,
      float* __restrict__ out) {
    const int tid   = threadIdx.x;
    const int b     = blockIdx.x;
    const int n     = b / BPN;
    const int local = b % BPN;
    const int s2    = (PH2_ * local) / BPN;
    const int e2    = (PH2_ * (local + 1)) / BPN;
    const int lane  = tid & 31, wid = tid >> 5;

    __shared__ float sS[24], sMX[24], f_own[8], cn_own[8], acc_own[8], x0c[3];
    __shared__ float f_sav[8], s_Sold[24];
    __shared__ float sh_tauD, sh_lam, sh_gam;
    __shared__ float s_scl[64], s_sums[64], s_gt[64], s_tr[64];
    __shared__ float s_gram[8][8][8], s_x0[24], s_G[192], s_Sg[24], s_n3[8], s_tauS;
    __shared__ float sStS[64];
    __shared__ float sred[4 * 68];

    if (tid < 24) sS[tid] = Sin[tid];
    if (tid == 24) sh_gam = fabsf(gamma_[0]);
    if (tid == 25) sh_lam = fabsf(lam_[0]);
    if (tid < 8) { f_own[tid] = 0.f; acc_own[tid] = 0.f; }
    { int idx = b * NTHR + tid; if (idx < 3 * 544) g_stats[idx] = 0.f; }

    const float2* Xp2 = reinterpret_cast<const float2*>(X) + (size_t)n * 3 * PH2_;
    uint2* Dq = reinterpret_cast<uint2*>(g_dt) + (size_t)n * 4 * PH2_;
    float2* Op2 = reinterpret_cast<float2*>(out + 48) + (size_t)n * 8 * PH2_;

    // ---- meanX partials over own range ----
    {
        float m0 = 0.f, m1 = 0.f, m2 = 0.f;
        for (int i = s2 + tid; i < e2; i += NTHR) {
            float2 a = Xp2[i], bb = Xp2[i + PH2_], c = Xp2[i + 2 * PH2_];
            m0 += a.x + a.y;
            m1 += bb.x + bb.y;
            m2 += c.x + c.y;
        }
        #pragma unroll
        for (int o = 16; o; o >>= 1) {
            m0 += __shfl_xor_sync(~0u, m0, o);
            m1 += __shfl_xor_sync(~0u, m1, o);
            m2 += __shfl_xor_sync(~0u, m2, o);
        }
        if (lane == 0) { sred[wid * 3 + 0] = m0; sred[wid * 3 + 1] = m1; sred[wid * 3 + 2] = m2; }
        __syncthreads();
        if (tid < 3) {
            float s = 0.f;
            #pragma unroll
            for (int w = 0; w < 4; w++) s += sred[w * 3 + tid];
            g_meanx[b * 3 + tid] = s;
        }
    }

    gridsync();   // zeroed stats + meanx partials visible

    if (tid < 24) {
        int nn = tid / 3, cc = tid % 3;
        float s = 0.f;
        for (int j = 0; j < BPN; j++) s += g_meanx[(nn * BPN + j) * 3 + cc];
        sMX[tid] = s;
    }
    __syncthreads();
    const float lam = sh_lam, gam = sh_gam;

    do_iterA(tid, n, sS, sMX, f_own, acc_own, cn_own, sStS, x0c, &sh_tauD, lam, gam);

    for (int it = 0; it < 3; it++) {
        float* dst = &g_stats[it * 544 + n * 68];
        if (it == 0)      run_pass<0>(Xp2, Dq, s2, e2, tid, lane, wid, sS, f_own, cn_own, sh_tauD, sred, dst);
        else if (it == 1) run_pass<1>(Xp2, Dq, s2, e2, tid, lane, wid, sS, f_own, cn_own, sh_tauD, sred, dst);
        else              run_pass<2>(Xp2, Dq, s2, e2, tid, lane, wid, sS, f_own, cn_own, sh_tauD, sred, dst);

        gridsync();   // stats of this iteration complete

        // ================= iterB (redundant per block) =================
        {
            const int last = (it == 2);
            const float* st = &g_stats[it * 544];
            const float tauD = sh_tauD;
            if (last) {
                if (tid < 8)  f_sav[tid]  = f_own[tid];
                if (tid < 24) s_Sold[tid] = sS[tid];
            }
            if (tid < 64) {
                int nn = tid >> 3, r = tid & 7;
                float gu = st[nn * 68 + 32 + triIdx(r, r)];
                float L2 = sqrtf(gu);
                float t = L2 - lam * tauD * sqrtf(sStS[r * 8 + r]);
                float scl = fmaxf(t, 0.f) / L2 + EPS_;        // faithful to source
                s_scl[tid] = scl;
                float su = scl * st[nn * 68 + r];
                s_sums[tid] = su;
                s_gt[tid] = gam * su + scl * L2;
                s_tr[tid] = scl * scl * gu;
            }
            __syncthreads();
            for (int idx = tid; idx < 512; idx += NTHR) {
                int nn = idx >> 6, r = (idx >> 3) & 7, r2 = idx & 7;
                int lo = min(r, r2), hi = max(r, r2);
                s_gram[nn][r][r2] = s_scl[nn * 8 + r] * s_scl[nn * 8 + r2] *
                                    st[nn * 68 + 32 + triIdx(lo, hi)];
            }
            __syncthreads();
            if (tid < 24) {
                int nn = tid / 3, c = tid % 3;
                float a = sMX[tid];
                #pragma unroll
                for (int r = 0; r < 8; r++) a += sS[c * 8 + r] * s_sums[nn * 8 + r];
                a *= (1.f / (float)P_);
                s_x0[tid] = a;
                if (last && b == 0) out[tid] = a;
            }
            if (tid == 64) {
                float s = 0.f;
                for (int k = 0; k < 64; k++) s += s_tr[k];
                s_tauS = 8.f / s;
            }
            __syncthreads();
            for (int idx = tid; idx < 192; idx += NTHR) {
                int nn = idx / 24, c = (idx / 8) % 3, r = idx & 7;
                float g = s_scl[nn * 8 + r] * st[nn * 68 + 8 + c * 8 + r];
                #pragma unroll
                for (int r2 = 0; r2 < 8; r2++) g += sS[c * 8 + r2] * s_gram[nn][r2][r];
                g -= s_x0[nn * 3 + c] * s_sums[nn * 8 + r];
                s_G[idx] = g;
            }
            __syncthreads();
            if (tid < 24) {
                int c = tid / 8, r = tid & 7;
                float mg = 0.f;
                #pragma unroll
                for (int nn = 0; nn < 8; nn++) mg += s_G[nn * 24 + c * 8 + r];
                mg *= 0.125f;
                s_Sg[tid] = sS[c * 8 + r] - s_tauS * mg;
            }
            __syncthreads();
            if (tid < 8) {
                int r = tid;
                float dn = 0.f;
                #pragma unroll
                for (int nn = 0; nn < 8; nn++) dn += s_gt[nn * 8 + r];
                dn *= 0.125f;
                float n2 = 0.f;
                #pragma unroll
                for (int c = 0; c < 3; c++) n2 += s_Sg[c * 8 + r] * s_Sg[c * 8 + r];
                n2 = sqrtf(n2);
                float t = n2 - lam * s_tauS * dn;
                float sclS = fmaxf(t, 0.f) / (n2 + EPS_);
                float sn[3]; float n3 = 0.f;
                #pragma unroll
                for (int c = 0; c < 3; c++) { sn[c] = s_Sg[c * 8 + r] * sclS; n3 += sn[c] * sn[c]; }
                n3 = sqrtf(n3);
                s_n3[r] = n3;
                float inv = 1.f / (n3 + EPS_);
                #pragma unroll
                for (int c = 0; c < 3; c++) {
                    float nv = sn[c] * inv;
                    sS[c * 8 + r] = nv;
                    if (last && b == 0) out[24 + c * 8 + r] = nv;
                }
            }
            __syncthreads();
            if (tid < 8) {
                f_own[tid]   = s_scl[n * 8 + tid] * (s_n3[tid] + EPS_);
                acc_own[tid] = st[n * 68 + tid];
            }
            __syncthreads();
            if (!last)
                do_iterA(tid, n, sS, sMX, f_own, acc_own, cn_own, sStS, x0c, &sh_tauD, lam, gam);
        }
    }

    // ====== final pass: recompute it=2 values (pre-update S, saved fr/cn, same
    //        tauD — iterA skipped at last so sh_tauD/cn_own intact) and write
    //        f32 output scaled by the final lazy factor. ======
    {
        u64 Sp[12], frp[4], cnp[4], fsp[4];
        #pragma unroll
        for (int c = 0; c < 3; c++)
            #pragma unroll
            for (int rp = 0; rp < 4; rp++)
                Sp[c * 4 + rp] = pk2(s_Sold[c * 8 + 2 * rp], s_Sold[c * 8 + 2 * rp + 1]);
        #pragma unroll
        for (int rp = 0; rp < 4; rp++) {
            frp[rp] = pk2(f_sav[2 * rp], f_sav[2 * rp + 1]);
            cnp[rp] = pk2(cn_own[2 * rp], cn_own[2 * rp + 1]);
            fsp[rp] = pk2(f_own[2 * rp], f_own[2 * rp + 1]);
        }
        const float ntauD = -sh_tauD;

        for (int i = s2 + tid; i < e2; i += NTHR) {
            float2 xv0 = Xp2[i], xv1 = Xp2[i + PH2_], xv2 = Xp2[i + 2 * PH2_];
            uint2 dq[4];
            #pragma unroll
            for (int rp = 0; rp < 4; rp++) dq[rp] = Dq[i + rp * PH2_];
            float2 o[8];
            #pragma unroll
            for (int j = 0; j < 2; j++) {
                float x0 = j ? xv0.y : xv0.x;
                float x1 = j ? xv1.y : xv1.x;
                float x2 = j ? xv2.y : xv2.x;
                u64 dp[4];
                #pragma unroll
                for (int rp = 0; rp < 4; rp++)
                    dp[rp] = mul2_(frp[rp], h2f2(j ? dq[rp].y : dq[rp].x));
                u64 t0p = mul2_(Sp[0], dp[0]);
                t0p = fma2_(Sp[1], dp[1], t0p); t0p = fma2_(Sp[2], dp[2], t0p); t0p = fma2_(Sp[3], dp[3], t0p);
                u64 t1p = mul2_(Sp[4], dp[0]);
                t1p = fma2_(Sp[5], dp[1], t1p); t1p = fma2_(Sp[6], dp[2], t1p); t1p = fma2_(Sp[7], dp[3], t1p);
                u64 t2p = mul2_(Sp[8], dp[0]);
                t2p = fma2_(Sp[9], dp[1], t2p); t2p = fma2_(Sp[10], dp[2], t2p); t2p = fma2_(Sp[11], dp[3], t2p);
                F2 h0 = un2(t0p), h1 = un2(t1p), h2 = un2(t2p);
                float tc0 = ntauD * (x0 + h0.lo + h0.hi);
                float tc1 = ntauD * (x1 + h1.lo + h1.hi);
                float tc2 = ntauD * (x2 + h2.lo + h2.hi);
                u64 tb0 = pk2(tc0, tc0), tb1 = pk2(tc1, tc1), tb2 = pk2(tc2, tc2);
                #pragma unroll
                for (int rp = 0; rp < 4; rp++) {
                    u64 va = fma2_(tb0, Sp[rp], cnp[rp]);
                    va = fma2_(tb1, Sp[4 + rp], va);
                    va = fma2_(tb2, Sp[8 + rp], va);
                    va = add2_(va, dp[rp]);
                    u64 ov = mul2_(fsp[rp], relu2(va));
                    F2 f = un2(ov);
                    if (j) { o[2 * rp].y = f.lo; o[2 * rp + 1].y = f.hi; }
                    else   { o[2 * rp].x = f.lo; o[2 * rp + 1].x = f.hi; }
                }
            }
            #pragma unroll
            for (int r = 0; r < 8; r++) __stcs(&Op2[i + r * PH2_], o[r]);
        }
    }
}

extern "C" void kernel_launch(void* const* d_in, const int* in_sizes, int n_in,
                              void* d_out, int out_size) {
    const float* X     = (const float*)d_in[0];
    const float* S     = (const float*)d_in[1];
    const float* gamma = (const float*)d_in[2];
    const float* lam   = (const float*)d_in[3];
    float* out = (float*)d_out;
    k_all<<<NB, NTHR>>>(X, S, gamma, lam, out);
}

// round 6
// speedup vs baseline: 1.0757x; 1.0757x over previous
#include <cuda_runtime.h>
#include <cuda_fp16.h>
#include <math.h>

// Problem constants: N=8, C=3, R=8, P=512*512, n_iter=3
#define P_    262144
#define P4_   65536        // float4 count per plane
#define EPS_  1e-10f
#define NB    288          // total blocks (8 n-groups x 36); 2/SM co-resident (296 slots)
#define BPN   36
#define NTHR  128

// ---- device globals (no allocations allowed) ----
__device__ float    g_stats[3 * 544];     // per iter, per n: [0,8) sum, [8,32) XD, [32,68) gram-tri
__device__ float    g_meanx[NB * 3];
__device__ unsigned g_count = 0;
__device__ unsigned g_sense = 0;
__device__ __half2  g_dt[(size_t)64 * 131072];   // fp16 intermediate Dt, 8n x 8r planes

__device__ __forceinline__ int triIdx(int r, int r2) {   // r <= r2
    return r * 8 - (r * (r - 1)) / 2 + (r2 - r);
}
__device__ __forceinline__ float getc(const float4& v, int j) {
    return j == 0 ? v.x : j == 1 ? v.y : j == 2 ? v.z : v.w;
}
__device__ __forceinline__ void setc(float4& v, int j, float x) {
    if (j == 0) v.x = x; else if (j == 1) v.y = x; else if (j == 2) v.z = x; else v.w = x;
}
__device__ __forceinline__ float4 h4tof4(uint2 u) {
    __half2 a = *reinterpret_cast<__half2*>(&u.x);
    __half2 b = *reinterpret_cast<__half2*>(&u.y);
    float2 fa = __half22float2(a), fb = __half22float2(b);
    return make_float4(fa.x, fa.y, fb.x, fb.y);
}
__device__ __forceinline__ uint2 f4toh4(float4 v) {
    __half2 a = __floats2half2_rn(v.x, v.y);
    __half2 b = __floats2half2_rn(v.z, v.w);
    uint2 u;
    u.x = *reinterpret_cast<unsigned*>(&a);
    u.y = *reinterpret_cast<unsigned*>(&b);
    return u;
}
__device__ __forceinline__ unsigned ld_acq(unsigned* p) {
    unsigned v;
    asm volatile("ld.acquire.gpu.u32 %0, [%1];" : "=r"(v) : "l"(p) : "memory");
    return v;
}
// grid-wide sense-reversal barrier; all NB blocks co-resident by construction
__device__ __forceinline__ void gridsync() {
    __threadfence();
    __syncthreads();
    if (threadIdx.x == 0) {
        unsigned s0 = ld_acq(&g_sense);
        unsigned old = atomicAdd(&g_count, 1u);
        if (old == NB - 1) {
            atomicExch(&g_count, 0u);
            __threadfence();
            atomicAdd(&g_sense, 1u);
        } else {
            while (ld_acq(&g_sense) == s0) __nanosleep(64);
        }
    }
    __syncthreads();
}

// iterA: StS, tauD, x0(own n), cnst(own n). Redundant per block.
__device__ __forceinline__ void do_iterA(int tid, int n,
        const float* sS, const float* sMX, const float* f_own, const float* acc_own,
        float* cn_own, float* sStS, float* x0c, float* sh_tauD, float lam, float gam) {
    if (tid < 64) {
        int r = tid >> 3, r2 = tid & 7;
        float a = 0.f;
        #pragma unroll
        for (int c = 0; c < 3; c++) a += sS[c * 8 + r] * sS[c * 8 + r2];
        sStS[tid] = a;
    }
    __syncthreads();
    if (tid == 0) {
        float s = 0.f;
        #pragma unroll
        for (int r = 0; r < 8; r++) s += sStS[r * 8 + r];
        *sh_tauD = 1.f / s;
    }
    __syncthreads();
    float tauD = *sh_tauD;
    if (tid < 3) {
        float acc = sMX[n * 3 + tid];
        #pragma unroll
        for (int r = 0; r < 8; r++) acc += sS[tid * 8 + r] * f_own[r] * acc_own[r];
        x0c[tid] = acc * (1.f / (float)P_);
    }
    __syncthreads();
    if (tid < 8) {
        int r = tid;
        float bb = 0.f;
        #pragma unroll
        for (int c = 0; c < 3; c++) bb += sS[c * 8 + r] * x0c[c];
        cn_own[r] = tauD * bb - lam * gam * tauD * sqrtf(sStS[r * 8 + r]);
    }
    __syncthreads();
}

// ---------------------------------------------------------------------------
// run_pass: fused D-update + prox + stats, software-pipelined (double buffer).
//   MODE 0: no Dt read, store. MODE 1: read + store. MODE 2: read only.
// ---------------------------------------------------------------------------
template<int MODE>
__device__ __forceinline__ void run_pass(
    const float4* __restrict__ Xp, uint2* __restrict__ Dq,
    int s4, int e4, int tid, int lane, int wid,
    const float* sS, const float* f_own, const float* cn_own, float tauD,
    float* sred, float* dst)
{
    float Sc[24], fr[8], cn[8];
    #pragma unroll
    for (int k = 0; k < 24; k++) Sc[k] = sS[k];
    #pragma unroll
    for (int r = 0; r < 8; r++) { fr[r] = f_own[r]; cn[r] = cn_own[r]; }

    float a_s[8], a_x[24], a_g[36];
    #pragma unroll
    for (int k = 0; k < 8; k++)  a_s[k] = 0.f;
    #pragma unroll
    for (int k = 0; k < 24; k++) a_x[k] = 0.f;
    #pragma unroll
    for (int k = 0; k < 36; k++) a_g[k] = 0.f;

    // compute body on one prefetched point-group
    auto body = [&](int i, const float4& xv0, const float4& xv1, const float4& xv2,
                    const uint2* dq) {
        float4 dv[8];
        if (MODE != 0) {
            #pragma unroll
            for (int r = 0; r < 8; r++) dv[r] = h4tof4(dq[r]);
        }
        #pragma unroll
        for (int j = 0; j < 4; j++) {
            float x0 = getc(xv0, j), x1 = getc(xv1, j), x2 = getc(xv2, j);
            float v[8];
            if (MODE != 0) {
                float de[8];
                float t0 = x0, t1 = x1, t2 = x2;
                #pragma unroll
                for (int r = 0; r < 8; r++) {
                    float d = fr[r] * getc(dv[r], j);
                    de[r] = d;
                    t0 += Sc[r] * d;
                    t1 += Sc[8 + r] * d;
                    t2 += Sc[16 + r] * d;
                }
                #pragma unroll
                for (int r = 0; r < 8; r++) {
                    float u = Sc[r] * t0 + Sc[8 + r] * t1 + Sc[16 + r] * t2;
                    float val = fmaxf(de[r] + cn[r] - tauD * u, 0.f);
                    v[r] = val;
                    setc(dv[r], j, val);
                }
            } else {
                #pragma unroll
                for (int r = 0; r < 8; r++) {
                    float u = Sc[r] * x0 + Sc[8 + r] * x1 + Sc[16 + r] * x2;
                    float val = fmaxf(cn[r] - tauD * u, 0.f);
                    v[r] = val;
                    setc(dv[r], j, val);
                }
            }
            #pragma unroll
            for (int r = 0; r < 8; r++) {
                a_s[r]      += v[r];
                a_x[r]      += x0 * v[r];
                a_x[8 + r]  += x1 * v[r];
                a_x[16 + r] += x2 * v[r];
            }
            int gi = 0;
            #pragma unroll
            for (int r = 0; r < 8; r++)
                #pragma unroll
                for (int r2 = r; r2 < 8; r2++) { a_g[gi] += v[r] * v[r2]; gi++; }
        }
        if (MODE != 2) {
            #pragma unroll
            for (int r = 0; r < 8; r++) Dq[i + r * P4_] = f4toh4(dv[r]);
        }
    };

    int i = s4 + tid;
    if (i < e4) {
        float4 xA0, xA1, xA2, xB0, xB1, xB2;
        uint2 dA[8], dB[8];
        // prologue
        xA0 = Xp[i]; xA1 = Xp[i + P4_]; xA2 = Xp[i + 2 * P4_];
        if (MODE != 0) {
            #pragma unroll
            for (int r = 0; r < 8; r++) dA[r] = Dq[i + r * P4_];
        }
        int iA = i;
        while (true) {
            int iB = iA + NTHR;
            bool hasB = iB < e4;
            int ldB = hasB ? iB : iA;
            xB0 = Xp[ldB]; xB1 = Xp[ldB + P4_]; xB2 = Xp[ldB + 2 * P4_];
            if (MODE != 0) {
                #pragma unroll
                for (int r = 0; r < 8; r++) dB[r] = Dq[ldB + r * P4_];
            }
            body(iA, xA0, xA1, xA2, dA);
            if (!hasB) break;

            int iC = iB + NTHR;
            bool hasC = iC < e4;
            int ldC = hasC ? iC : iB;
            xA0 = Xp[ldC]; xA1 = Xp[ldC + P4_]; xA2 = Xp[ldC + 2 * P4_];
            if (MODE != 0) {
                #pragma unroll
                for (int r = 0; r < 8; r++) dA[r] = Dq[ldC + r * P4_];
            }
            body(iB, xB0, xB1, xB2, dB);
            if (!hasC) break;
            iA = iC;
        }
    }

    // ---- flush: warp shuffle -> smem -> one atomic per value ----
    __syncthreads();
    #pragma unroll
    for (int k = 0; k < 8; k++) {
        float vv = a_s[k];
        #pragma unroll
        for (int o = 16; o; o >>= 1) vv += __shfl_xor_sync(~0u, vv, o);
        if (lane == 0) sred[wid * 68 + k] = vv;
    }
    #pragma unroll
    for (int k = 0; k < 24; k++) {
        float vv = a_x[k];
        #pragma unroll
        for (int o = 16; o; o >>= 1) vv += __shfl_xor_sync(~0u, vv, o);
        if (lane == 0) sred[wid * 68 + 8 + k] = vv;
    }
    #pragma unroll
    for (int k = 0; k < 36; k++) {
        float vv = a_g[k];
        #pragma unroll
        for (int o = 16; o; o >>= 1) vv += __shfl_xor_sync(~0u, vv, o);
        if (lane == 0) sred[wid * 68 + 32 + k] = vv;
    }
    __syncthreads();
    if (tid < 68) {
        float s = sred[tid] + sred[68 + tid] + sred[136 + tid] + sred[204 + tid];
        atomicAdd(&dst[tid], s);
    }
}

__global__ void __launch_bounds__(NTHR, 2)
k_all(const float* __restrict__ X, const float* __restrict__ Sin,
      const float* __restrict__ gamma_, const float* __restrict__ lam_,
      float* __restrict__ out) {
    const int tid   = threadIdx.x;
    const int b     = blockIdx.x;
    const int n     = b / BPN;
    const int local = b % BPN;
    const int s4    = (P4_ * local) / BPN;
    const int e4    = (P4_ * (local + 1)) / BPN;
    const int lane  = tid & 31, wid = tid >> 5;

    __shared__ float sS[24], sMX[24], f_own[8], cn_own[8], acc_own[8], x0c[3];
    __shared__ float f_sav[8], s_Sold[24];
    __shared__ float sh_tauD, sh_lam, sh_gam;
    __shared__ float s_scl[64], s_sums[64], s_gt[64], s_tr[64];
    __shared__ float s_gram[8][8][8], s_x0[24], s_G[192], s_Sg[24], s_n3[8], s_tauS;
    __shared__ float sStS[64];
    __shared__ float sred[4 * 68];

    if (tid < 24) sS[tid] = Sin[tid];
    if (tid == 24) sh_gam = fabsf(gamma_[0]);
    if (tid == 25) sh_lam = fabsf(lam_[0]);
    if (tid < 8) { f_own[tid] = 0.f; acc_own[tid] = 0.f; }
    { int idx = b * NTHR + tid; if (idx < 3 * 544) g_stats[idx] = 0.f; }

    const float4* Xp = reinterpret_cast<const float4*>(X) + (size_t)n * 3 * P4_;
    uint2* Dq = reinterpret_cast<uint2*>(g_dt) + (size_t)n * 8 * P4_;
    float4* Dpout = reinterpret_cast<float4*>(out + 48) + (size_t)n * 8 * P4_;

    // ---- meanX partials over own range ----
    {
        float m0 = 0.f, m1 = 0.f, m2 = 0.f;
        for (int i = s4 + tid; i < e4; i += NTHR) {
            float4 a = Xp[i], bb = Xp[i + P4_], c = Xp[i + 2 * P4_];
            m0 += a.x + a.y + a.z + a.w;
            m1 += bb.x + bb.y + bb.z + bb.w;
            m2 += c.x + c.y + c.z + c.w;
        }
        #pragma unroll
        for (int o = 16; o; o >>= 1) {
            m0 += __shfl_xor_sync(~0u, m0, o);
            m1 += __shfl_xor_sync(~0u, m1, o);
            m2 += __shfl_xor_sync(~0u, m2, o);
        }
        if (lane == 0) { sred[wid * 3 + 0] = m0; sred[wid * 3 + 1] = m1; sred[wid * 3 + 2] = m2; }
        __syncthreads();
        if (tid < 3) {
            float s = 0.f;
            #pragma unroll
            for (int w = 0; w < 4; w++) s += sred[w * 3 + tid];
            g_meanx[b * 3 + tid] = s;
        }
    }

    gridsync();   // zeroed stats + meanx partials visible

    if (tid < 24) {
        int nn = tid / 3, cc = tid % 3;
        float s = 0.f;
        for (int j = 0; j < BPN; j++) s += g_meanx[(nn * BPN + j) * 3 + cc];
        sMX[tid] = s;
    }
    __syncthreads();
    const float lam = sh_lam, gam = sh_gam;

    do_iterA(tid, n, sS, sMX, f_own, acc_own, cn_own, sStS, x0c, &sh_tauD, lam, gam);

    for (int it = 0; it < 3; it++) {
        float* dst = &g_stats[it * 544 + n * 68];
        if (it == 0)      run_pass<0>(Xp, Dq, s4, e4, tid, lane, wid, sS, f_own, cn_own, sh_tauD, sred, dst);
        else if (it == 1) run_pass<1>(Xp, Dq, s4, e4, tid, lane, wid, sS, f_own, cn_own, sh_tauD, sred, dst);
        else              run_pass<2>(Xp, Dq, s4, e4, tid, lane, wid, sS, f_own, cn_own, sh_tauD, sred, dst);

        gridsync();   // stats of this iteration complete

        // ================= iterB (redundant per block) =================
        {
            const int last = (it == 2);
            const float* st = &g_stats[it * 544];
            const float tauD = sh_tauD;
            if (last) {
                if (tid < 8)  f_sav[tid]  = f_own[tid];
                if (tid < 24) s_Sold[tid] = sS[tid];
            }
            if (tid < 64) {
                int nn = tid >> 3, r = tid & 7;
                float gu = st[nn * 68 + 32 + triIdx(r, r)];
                float L2 = sqrtf(gu);
                float t = L2 - lam * tauD * sqrtf(sStS[r * 8 + r]);
                float scl = fmaxf(t, 0.f) / L2 + EPS_;        // faithful to source
                s_scl[tid] = scl;
                float su = scl * st[nn * 68 + r];
                s_sums[tid] = su;
                s_gt[tid] = gam * su + scl * L2;
                s_tr[tid] = scl * scl * gu;
            }
            __syncthreads();
            for (int idx = tid; idx < 512; idx += NTHR) {
                int nn = idx >> 6, r = (idx >> 3) & 7, r2 = idx & 7;
                int lo = min(r, r2), hi = max(r, r2);
                s_gram[nn][r][r2] = s_scl[nn * 8 + r] * s_scl[nn * 8 + r2] *
                                    st[nn * 68 + 32 + triIdx(lo, hi)];
            }
            __syncthreads();
            if (tid < 24) {
                int nn = tid / 3, c = tid % 3;
                float a = sMX[tid];
                #pragma unroll
                for (int r = 0; r < 8; r++) a += sS[c * 8 + r] * s_sums[nn * 8 + r];
                a *= (1.f / (float)P_);
                s_x0[tid] = a;
                if (last && b == 0) out[tid] = a;
            }
            if (tid == 64) {
                float s = 0.f;
                for (int k = 0; k < 64; k++) s += s_tr[k];
                s_tauS = 8.f / s;
            }
            __syncthreads();
            for (int idx = tid; idx < 192; idx += NTHR) {
                int nn = idx / 24, c = (idx / 8) % 3, r = idx & 7;
                float g = s_scl[nn * 8 + r] * st[nn * 68 + 8 + c * 8 + r];
                #pragma unroll
                for (int r2 = 0; r2 < 8; r2++) g += sS[c * 8 + r2] * s_gram[nn][r2][r];
                g -= s_x0[nn * 3 + c] * s_sums[nn * 8 + r];
                s_G[idx] = g;
            }
            __syncthreads();
            if (tid < 24) {
                int c = tid / 8, r = tid & 7;
                float mg = 0.f;
                #pragma unroll
                for (int nn = 0; nn < 8; nn++) mg += s_G[nn * 24 + c * 8 + r];
                mg *= 0.125f;
                s_Sg[tid] = sS[c * 8 + r] - s_tauS * mg;
            }
            __syncthreads();
            if (tid < 8) {
                int r = tid;
                float dn = 0.f;
                #pragma unroll
                for (int nn = 0; nn < 8; nn++) dn += s_gt[nn * 8 + r];
                dn *= 0.125f;
                float n2 = 0.f;
                #pragma unroll
                for (int c = 0; c < 3; c++) n2 += s_Sg[c * 8 + r] * s_Sg[c * 8 + r];
                n2 = sqrtf(n2);
                float t = n2 - lam * s_tauS * dn;
                float sclS = fmaxf(t, 0.f) / (n2 + EPS_);
                float sn[3]; float n3 = 0.f;
                #pragma unroll
                for (int c = 0; c < 3; c++) { sn[c] = s_Sg[c * 8 + r] * sclS; n3 += sn[c] * sn[c]; }
                n3 = sqrtf(n3);
                s_n3[r] = n3;
                float inv = 1.f / (n3 + EPS_);
                #pragma unroll
                for (int c = 0; c < 3; c++) {
                    float nv = sn[c] * inv;
                    sS[c * 8 + r] = nv;
                    if (last && b == 0) out[24 + c * 8 + r] = nv;
                }
            }
            __syncthreads();
            if (tid < 8) {
                f_own[tid]   = s_scl[n * 8 + tid] * (s_n3[tid] + EPS_);
                acc_own[tid] = st[n * 68 + tid];
            }
            __syncthreads();
            if (!last)
                do_iterA(tid, n, sS, sMX, f_own, acc_own, cn_own, sStS, x0c, &sh_tauD, lam, gam);
        }
    }

    // ====== final pass: recompute it=2 values (pre-update S, saved fr/cn,
    //        same tauD) and write f32 output scaled by the final lazy factor.
    //        Software-pipelined like run_pass. ======
    {
        float Sc[24], fr[8], cn[8], fs[8];
        #pragma unroll
        for (int k = 0; k < 24; k++) Sc[k] = s_Sold[k];
        #pragma unroll
        for (int r = 0; r < 8; r++) {
            fr[r] = f_sav[r];
            cn[r] = cn_own[r];
            fs[r] = f_own[r];
        }
        const float tauD = sh_tauD;

        auto fbody = [&](int i, const float4& xv0, const float4& xv1, const float4& xv2,
                         const uint2* dq) {
            float4 dv[8];
            #pragma unroll
            for (int r = 0; r < 8; r++) dv[r] = h4tof4(dq[r]);
            #pragma unroll
            for (int j = 0; j < 4; j++) {
                float x0 = getc(xv0, j), x1 = getc(xv1, j), x2 = getc(xv2, j);
                float de[8];
                float t0 = x0, t1 = x1, t2 = x2;
                #pragma unroll
                for (int r = 0; r < 8; r++) {
                    float d = fr[r] * getc(dv[r], j);
                    de[r] = d;
                    t0 += Sc[r] * d;
                    t1 += Sc[8 + r] * d;
                    t2 += Sc[16 + r] * d;
                }
                #pragma unroll
                for (int r = 0; r < 8; r++) {
                    float u = Sc[r] * t0 + Sc[8 + r] * t1 + Sc[16 + r] * t2;
                    float val = fmaxf(de[r] + cn[r] - tauD * u, 0.f);
                    setc(dv[r], j, val * fs[r]);
                }
            }
            #pragma unroll
            for (int r = 0; r < 8; r++) __stcs(&Dpout[i + r * P4_], dv[r]);
        };

        int i = s4 + tid;
        if (i < e4) {
            float4 xA0, xA1, xA2, xB0, xB1, xB2;
            uint2 dA[8], dB[8];
            xA0 = Xp[i]; xA1 = Xp[i + P4_]; xA2 = Xp[i + 2 * P4_];
            #pragma unroll
            for (int r = 0; r < 8; r++) dA[r] = Dq[i + r * P4_];
            int iA = i;
            while (true) {
                int iB = iA + NTHR;
                bool hasB = iB < e4;
                int ldB = hasB ? iB : iA;
                xB0 = Xp[ldB]; xB1 = Xp[ldB + P4_]; xB2 = Xp[ldB + 2 * P4_];
                #pragma unroll
                for (int r = 0; r < 8; r++) dB[r] = Dq[ldB + r * P4_];
                fbody(iA, xA0, xA1, xA2, dA);
                if (!hasB) break;

                int iC = iB + NTHR;
                bool hasC = iC < e4;
                int ldC = hasC ? iC : iB;
                xA0 = Xp[ldC]; xA1 = Xp[ldC + P4_]; xA2 = Xp[ldC + 2 * P4_];
                #pragma unroll
                for (int r = 0; r < 8; r++) dA[r] = Dq[ldC + r * P4_];
                fbody(iB, xB0, xB1, xB2, dB);
                if (!hasC) break;
                iA = iC;
            }
        }
    }
}

extern "C" void kernel_launch(void* const* d_in, const int* in_sizes, int n_in,
                              void* d_out, int out_size) {
    const float* X     = (const float*)d_in[0];
    const float* S     = (const float*)d_in[1];
    const float* gamma = (const float*)d_in[2];
    const float* lam   = (const float*)d_in[3];
    float* out = (float*)d_out;
    k_all<<<NB, NTHR>>>(X, S, gamma, lam, out);
}

// round 7
// speedup vs baseline: 1.0913x; 1.0145x over previous
#include <cuda_runtime.h>
#include <cuda_fp16.h>
#include <math.h>

// Problem constants: N=8, C=3, R=8, P=512*512, n_iter=3
#define P_    262144
#define P4_   65536        // float4 count per plane
#define EPS_  1e-10f
#define NB    440          // total blocks (8 n-groups x 55); 3/SM co-resident
#define BPN   55
#define NTHR  128

// ---- device globals (no allocations allowed) ----
__device__ float    g_stats[3 * 544];     // per iter, per n: [0,8) sum, [8,32) XD, [32,68) gram-tri
__device__ float    g_meanx[NB * 3];
__device__ unsigned g_count = 0;
__device__ unsigned g_sense = 0;
__device__ __half2  g_dt[(size_t)64 * 131072];   // fp16 intermediate Dt, 8n x 8r planes

__device__ __forceinline__ int triIdx(int r, int r2) {   // r <= r2
    return r * 8 - (r * (r - 1)) / 2 + (r2 - r);
}
__device__ __forceinline__ float getc(const float4& v, int j) {
    return j == 0 ? v.x : j == 1 ? v.y : j == 2 ? v.z : v.w;
}
__device__ __forceinline__ void setc(float4& v, int j, float x) {
    if (j == 0) v.x = x; else if (j == 1) v.y = x; else if (j == 2) v.z = x; else v.w = x;
}
__device__ __forceinline__ float4 h4tof4(uint2 u) {
    __half2 a = *reinterpret_cast<__half2*>(&u.x);
    __half2 b = *reinterpret_cast<__half2*>(&u.y);
    float2 fa = __half22float2(a), fb = __half22float2(b);
    return make_float4(fa.x, fa.y, fb.x, fb.y);
}
__device__ __forceinline__ uint2 f4toh4(float4 v) {
    __half2 a = __floats2half2_rn(v.x, v.y);
    __half2 b = __floats2half2_rn(v.z, v.w);
    uint2 u;
    u.x = *reinterpret_cast<unsigned*>(&a);
    u.y = *reinterpret_cast<unsigned*>(&b);
    return u;
}
__device__ __forceinline__ unsigned ld_acq(unsigned* p) {
    unsigned v;
    asm volatile("ld.acquire.gpu.u32 %0, [%1];" : "=r"(v) : "l"(p) : "memory");
    return v;
}
// grid-wide sense-reversal barrier; all NB blocks co-resident by construction
__device__ __forceinline__ void gridsync() {
    __threadfence();
    __syncthreads();
    if (threadIdx.x == 0) {
        unsigned s0 = ld_acq(&g_sense);
        unsigned old = atomicAdd(&g_count, 1u);
        if (old == NB - 1) {
            atomicExch(&g_count, 0u);
            __threadfence();
            atomicAdd(&g_sense, 1u);
        } else {
            while (ld_acq(&g_sense) == s0) __nanosleep(64);
        }
    }
    __syncthreads();
}

// iterA: StS, tauD, x0(own n), cnst(own n). Redundant per block.
__device__ __forceinline__ void do_iterA(int tid, int n,
        const float* sS, const float* sMX, const float* f_own, const float* acc_own,
        float* cn_own, float* sStS, float* x0c, float* sh_tauD, float lam, float gam) {
    if (tid < 64) {
        int r = tid >> 3, r2 = tid & 7;
        float a = 0.f;
        #pragma unroll
        for (int c = 0; c < 3; c++) a += sS[c * 8 + r] * sS[c * 8 + r2];
        sStS[tid] = a;
    }
    __syncthreads();
    if (tid == 0) {
        float s = 0.f;
        #pragma unroll
        for (int r = 0; r < 8; r++) s += sStS[r * 8 + r];
        *sh_tauD = 1.f / s;
    }
    __syncthreads();
    float tauD = *sh_tauD;
    if (tid < 3) {
        float acc = sMX[n * 3 + tid];
        #pragma unroll
        for (int r = 0; r < 8; r++) acc += sS[tid * 8 + r] * f_own[r] * acc_own[r];
        x0c[tid] = acc * (1.f / (float)P_);
    }
    __syncthreads();
    if (tid < 8) {
        int r = tid;
        float bb = 0.f;
        #pragma unroll
        for (int c = 0; c < 3; c++) bb += sS[c * 8 + r] * x0c[c];
        cn_own[r] = tauD * bb - lam * gam * tauD * sqrtf(sStS[r * 8 + r]);
    }
    __syncthreads();
}

// ---------------------------------------------------------------------------
// run_pass: fused D-update + prox + stats (round-4 proven loop).
//   FIRST=1: no Dt read. Always stores fp16 Dt.
// ---------------------------------------------------------------------------
template<int FIRST>
__device__ __forceinline__ void run_pass(
    const float4* __restrict__ Xp, uint2* __restrict__ Dq,
    int s4, int e4, int tid, int lane, int wid,
    const float* sS, const float* f_own, const float* cn_own, float tauD,
    float* sred, float* dst)
{
    float Sc[24], fr[8], cn[8];
    #pragma unroll
    for (int k = 0; k < 24; k++) Sc[k] = sS[k];
    #pragma unroll
    for (int r = 0; r < 8; r++) { fr[r] = f_own[r]; cn[r] = cn_own[r]; }

    float a_s[8], a_x[24], a_g[36];
    #pragma unroll
    for (int k = 0; k < 8; k++)  a_s[k] = 0.f;
    #pragma unroll
    for (int k = 0; k < 24; k++) a_x[k] = 0.f;
    #pragma unroll
    for (int k = 0; k < 36; k++) a_g[k] = 0.f;

    for (int i = s4 + tid; i < e4; i += NTHR) {
        float4 xv0 = Xp[i], xv1 = Xp[i + P4_], xv2 = Xp[i + 2 * P4_];
        float4 dv[8];
        if (!FIRST) {
            #pragma unroll
            for (int r = 0; r < 8; r++) dv[r] = h4tof4(Dq[i + r * P4_]);
        }
        #pragma unroll
        for (int j = 0; j < 4; j++) {
            float x0 = getc(xv0, j), x1 = getc(xv1, j), x2 = getc(xv2, j);
            float v[8];
            if (!FIRST) {
                float de[8];
                float t0 = x0, t1 = x1, t2 = x2;
                #pragma unroll
                for (int r = 0; r < 8; r++) {
                    float d = fr[r] * getc(dv[r], j);
                    de[r] = d;
                    t0 += Sc[r] * d;
                    t1 += Sc[8 + r] * d;
                    t2 += Sc[16 + r] * d;
                }
                #pragma unroll
                for (int r = 0; r < 8; r++) {
                    float u = Sc[r] * t0 + Sc[8 + r] * t1 + Sc[16 + r] * t2;
                    float val = fmaxf(de[r] + cn[r] - tauD * u, 0.f);
                    v[r] = val;
                    setc(dv[r], j, val);
                }
            } else {
                #pragma unroll
                for (int r = 0; r < 8; r++) {
                    float u = Sc[r] * x0 + Sc[8 + r] * x1 + Sc[16 + r] * x2;
                    float val = fmaxf(cn[r] - tauD * u, 0.f);
                    v[r] = val;
                    setc(dv[r], j, val);
                }
            }
            #pragma unroll
            for (int r = 0; r < 8; r++) {
                a_s[r]      += v[r];
                a_x[r]      += x0 * v[r];
                a_x[8 + r]  += x1 * v[r];
                a_x[16 + r] += x2 * v[r];
            }
            int gi = 0;
            #pragma unroll
            for (int r = 0; r < 8; r++)
                #pragma unroll
                for (int r2 = r; r2 < 8; r2++) { a_g[gi] += v[r] * v[r2]; gi++; }
        }
        #pragma unroll
        for (int r = 0; r < 8; r++) Dq[i + r * P4_] = f4toh4(dv[r]);
    }

    // ---- flush: warp shuffle -> smem -> one atomic per value ----
    __syncthreads();
    #pragma unroll
    for (int k = 0; k < 8; k++) {
        float vv = a_s[k];
        #pragma unroll
        for (int o = 16; o; o >>= 1) vv += __shfl_xor_sync(~0u, vv, o);
        if (lane == 0) sred[wid * 68 + k] = vv;
    }
    #pragma unroll
    for (int k = 0; k < 24; k++) {
        float vv = a_x[k];
        #pragma unroll
        for (int o = 16; o; o >>= 1) vv += __shfl_xor_sync(~0u, vv, o);
        if (lane == 0) sred[wid * 68 + 8 + k] = vv;
    }
    #pragma unroll
    for (int k = 0; k < 36; k++) {
        float vv = a_g[k];
        #pragma unroll
        for (int o = 16; o; o >>= 1) vv += __shfl_xor_sync(~0u, vv, o);
        if (lane == 0) sred[wid * 68 + 32 + k] = vv;
    }
    __syncthreads();
    if (tid < 68) {
        float s = sred[tid] + sred[68 + tid] + sred[136 + tid] + sred[204 + tid];
        atomicAdd(&dst[tid], s);
    }
}

__global__ void __launch_bounds__(NTHR, 3)
k_all(const float* __restrict__ X, const float* __restrict__ Sin,
      const float* __restrict__ gamma_, const float* __restrict__ lam_,
      float* __restrict__ out) {
    const int tid   = threadIdx.x;
    const int b     = blockIdx.x;
    const int n     = b / BPN;
    const int local = b % BPN;
    const int s4    = (P4_ * local) / BPN;
    const int e4    = (P4_ * (local + 1)) / BPN;
    const int lane  = tid & 31, wid = tid >> 5;

    __shared__ float sS[24], sMX[24], f_own[8], cn_own[8], acc_own[8], x0c[3];
    __shared__ float sh_tauD, sh_lam, sh_gam;
    __shared__ float s_scl[64], s_sums[64], s_gt[64], s_tr[64];
    __shared__ float s_gram[8][8][8], s_x0[24], s_G[192], s_Sg[24], s_n3[8], s_tauS;
    __shared__ float sStS[64];
    __shared__ float sred[4 * 68];

    if (tid < 24) sS[tid] = Sin[tid];
    if (tid == 24) sh_gam = fabsf(gamma_[0]);
    if (tid == 25) sh_lam = fabsf(lam_[0]);
    if (tid < 8) { f_own[tid] = 0.f; acc_own[tid] = 0.f; }
    { int idx = b * NTHR + tid; if (idx < 3 * 544) g_stats[idx] = 0.f; }

    const float4* Xp = reinterpret_cast<const float4*>(X) + (size_t)n * 3 * P4_;
    uint2* Dq = reinterpret_cast<uint2*>(g_dt) + (size_t)n * 8 * P4_;
    float4* Dpout = reinterpret_cast<float4*>(out + 48) + (size_t)n * 8 * P4_;

    // ---- meanX partials over own range ----
    {
        float m0 = 0.f, m1 = 0.f, m2 = 0.f;
        for (int i = s4 + tid; i < e4; i += NTHR) {
            float4 a = Xp[i], bb = Xp[i + P4_], c = Xp[i + 2 * P4_];
            m0 += a.x + a.y + a.z + a.w;
            m1 += bb.x + bb.y + bb.z + bb.w;
            m2 += c.x + c.y + c.z + c.w;
        }
        #pragma unroll
        for (int o = 16; o; o >>= 1) {
            m0 += __shfl_xor_sync(~0u, m0, o);
            m1 += __shfl_xor_sync(~0u, m1, o);
            m2 += __shfl_xor_sync(~0u, m2, o);
        }
        if (lane == 0) { sred[wid * 3 + 0] = m0; sred[wid * 3 + 1] = m1; sred[wid * 3 + 2] = m2; }
        __syncthreads();
        if (tid < 3) {
            float s = 0.f;
            #pragma unroll
            for (int w = 0; w < 4; w++) s += sred[w * 3 + tid];
            g_meanx[b * 3 + tid] = s;
        }
    }

    gridsync();   // zeroed stats + meanx partials visible

    if (tid < 24) {
        int nn = tid / 3, cc = tid % 3;
        float s = 0.f;
        for (int j = 0; j < BPN; j++) s += g_meanx[(nn * BPN + j) * 3 + cc];
        sMX[tid] = s;
    }
    __syncthreads();
    const float lam = sh_lam, gam = sh_gam;

    do_iterA(tid, n, sS, sMX, f_own, acc_own, cn_own, sStS, x0c, &sh_tauD, lam, gam);

    for (int it = 0; it < 3; it++) {
        float* dst = &g_stats[it * 544 + n * 68];
        if (it == 0) run_pass<1>(Xp, Dq, s4, e4, tid, lane, wid, sS, f_own, cn_own, sh_tauD, sred, dst);
        else         run_pass<0>(Xp, Dq, s4, e4, tid, lane, wid, sS, f_own, cn_own, sh_tauD, sred, dst);

        gridsync();   // stats of this iteration complete

        // ================= iterB (redundant per block) =================
        {
            const int last = (it == 2);
            const float* st = &g_stats[it * 544];
            const float tauD = sh_tauD;
            if (tid < 64) {
                int nn = tid >> 3, r = tid & 7;
                float gu = st[nn * 68 + 32 + triIdx(r, r)];
                float L2 = sqrtf(gu);
                float t = L2 - lam * tauD * sqrtf(sStS[r * 8 + r]);
                float scl = fmaxf(t, 0.f) / L2 + EPS_;        // faithful to source
                s_scl[tid] = scl;
                float su = scl * st[nn * 68 + r];
                s_sums[tid] = su;
                s_gt[tid] = gam * su + scl * L2;
                s_tr[tid] = scl * scl * gu;
            }
            __syncthreads();
            for (int idx = tid; idx < 512; idx += NTHR) {
                int nn = idx >> 6, r = (idx >> 3) & 7, r2 = idx & 7;
                int lo = min(r, r2), hi = max(r, r2);
                s_gram[nn][r][r2] = s_scl[nn * 8 + r] * s_scl[nn * 8 + r2] *
                                    st[nn * 68 + 32 + triIdx(lo, hi)];
            }
            __syncthreads();
            if (tid < 24) {
                int nn = tid / 3, c = tid % 3;
                float a = sMX[tid];
                #pragma unroll
                for (int r = 0; r < 8; r++) a += sS[c * 8 + r] * s_sums[nn * 8 + r];
                a *= (1.f / (float)P_);
                s_x0[tid] = a;
                if (last && b == 0) out[tid] = a;
            }
            if (tid == 64) {
                float s = 0.f;
                for (int k = 0; k < 64; k++) s += s_tr[k];
                s_tauS = 8.f / s;
            }
            __syncthreads();
            for (int idx = tid; idx < 192; idx += NTHR) {
                int nn = idx / 24, c = (idx / 8) % 3, r = idx & 7;
                float g = s_scl[nn * 8 + r] * st[nn * 68 + 8 + c * 8 + r];
                #pragma unroll
                for (int r2 = 0; r2 < 8; r2++) g += sS[c * 8 + r2] * s_gram[nn][r2][r];
                g -= s_x0[nn * 3 + c] * s_sums[nn * 8 + r];
                s_G[idx] = g;
            }
            __syncthreads();
            if (tid < 24) {
                int c = tid / 8, r = tid & 7;
                float mg = 0.f;
                #pragma unroll
                for (int nn = 0; nn < 8; nn++) mg += s_G[nn * 24 + c * 8 + r];
                mg *= 0.125f;
                s_Sg[tid] = sS[c * 8 + r] - s_tauS * mg;
            }
            __syncthreads();
            if (tid < 8) {
                int r = tid;
                float dn = 0.f;
                #pragma unroll
                for (int nn = 0; nn < 8; nn++) dn += s_gt[nn * 8 + r];
                dn *= 0.125f;
                float n2 = 0.f;
                #pragma unroll
                for (int c = 0; c < 3; c++) n2 += s_Sg[c * 8 + r] * s_Sg[c * 8 + r];
                n2 = sqrtf(n2);
                float t = n2 - lam * s_tauS * dn;
                float sclS = fmaxf(t, 0.f) / (n2 + EPS_);
                float sn[3]; float n3 = 0.f;
                #pragma unroll
                for (int c = 0; c < 3; c++) { sn[c] = s_Sg[c * 8 + r] * sclS; n3 += sn[c] * sn[c]; }
                n3 = sqrtf(n3);
                s_n3[r] = n3;
                float inv = 1.f / (n3 + EPS_);
                #pragma unroll
                for (int c = 0; c < 3; c++) {
                    float nv = sn[c] * inv;
                    sS[c * 8 + r] = nv;
                    if (last && b == 0) out[24 + c * 8 + r] = nv;
                }
            }
            __syncthreads();
            if (tid < 8) {
                f_own[tid]   = s_scl[n * 8 + tid] * (s_n3[tid] + EPS_);
                acc_own[tid] = st[n * 68 + tid];
            }
            __syncthreads();
            if (!last)
                do_iterA(tid, n, sS, sMX, f_own, acc_own, cn_own, sStS, x0c, &sh_tauD, lam, gam);
        }
    }

    // ====== final scale pass: out = f * fp16(Dt_it2), own range (L2-hot). ======
    {
        float fs[8];
        #pragma unroll
        for (int r = 0; r < 8; r++) fs[r] = f_own[r];
        for (int i = s4 + tid; i < e4; i += NTHR) {
            uint2 dq[8];
            #pragma unroll
            for (int r = 0; r < 8; r++) dq[r] = Dq[i + r * P4_];
            #pragma unroll
            for (int r = 0; r < 8; r++) {
                float4 v = h4tof4(dq[r]);
                v.x *= fs[r]; v.y *= fs[r]; v.z *= fs[r]; v.w *= fs[r];
                __stcs(&Dpout[i + r * P4_], v);
            }
        }
    }
}

extern "C" void kernel_launch(void* const* d_in, const int* in_sizes, int n_in,
                              void* d_out, int out_size) {
    const float* X     = (const float*)d_in[0];
    const float* S     = (const float*)d_in[1];
    const float* gamma = (const float*)d_in[2];
    const float* lam   = (const float*)d_in[3];
    float* out = (float*)d_out;
    k_all<<<NB, NTHR>>>(X, S, gamma, lam, out);
}